// round 1
// baseline (speedup 1.0000x reference)
#include <cuda_runtime.h>
#include <math.h>

#define T_LEN   1000000
#define S_LEN    999999     // number of RK4 steps (T-1)
#define L_CH     27         // steps per chunk
#define NBLK     148
#define BLK      256
#define C1       (NBLK*BLK) // 37888 chunks
#define GRP      37         // chunks per group
#define C2       1024       // groups (GRP*C2 == C1)

// ---------------- scratch (__device__ globals; no allocations) ----------------
__device__ float4 g_F [C1*3];
__device__ float4 g_G [C1*3];
__device__ float4 g_H [C2*3];
__device__ float4 g_P0[C2*3];
__device__ float4 g_P1[C2*3];
__device__ float4 g_Pf[C2*3];

__device__ float g_Mcol[144];     // column-major fp32
__device__ float g_MLcol[144];    // M^27 column-major
__device__ float g_Wcol[10*144];  // (M^999)^(2^k), k=0..9, column-major
__device__ float g_ptv[12], g_qtv[12], g_vv[12];

// fp64 setup scratch
__device__ double dA_[144], dA2_[144], dA3_[144], dA4_[144];
__device__ double dM_[144], dP2_[144], dP4_[144], dP8_[144], dP16_[144];
__device__ double dT1_[144], dT2_[144], dML_[144];
__device__ double dW_[10][144];

// 12x12 fp64 matmul, one element per thread (t<144), block-synchronized
__device__ __forceinline__ void mm144(double* dst, const double* a, const double* b, int t) {
    double s = 0.0;
    if (t < 144) {
        int r = t / 12, c = t % 12;
        #pragma unroll
        for (int k = 0; k < 12; k++) s += a[r*12+k] * b[k*12+c];
    }
    if (t < 144) dst[t] = s;
    __syncthreads();
}

// ---------------- K0: setup (fp64 -> fp32) ----------------
__global__ void k_setup(const float* __restrict__ t_eval, const float* __restrict__ A,
                        const float* __restrict__ B, const float* __restrict__ loads_raw,
                        const float* __restrict__ room_areas) {
    __shared__ double sQw[10], sb0[12], sBq[12];
    __shared__ double sh;
    int t = threadIdx.x;

    if (t == 0) sh = (double)t_eval[1] - (double)t_eval[0];
    if (t < 10) {
        double x = (double)loads_raw[10 + t];               // gain_load row (action=0)
        sQw[t] = 1.0 / (1.0 + exp(-x)) * 50.0 * (double)room_areas[t];
    }
    if (t < 144) dA_[t] = (double)A[t];
    __syncthreads();

    if (t < 12) {
        sb0[t] = (double)B[t*11];
        double s = 0.0;
        #pragma unroll
        for (int j = 0; j < 10; j++) s += (double)B[t*11 + 1 + j] * sQw[j];
        sBq[t] = s;
    }
    __syncthreads();

    mm144(dA2_, dA_,  dA_, t);
    mm144(dA3_, dA2_, dA_, t);
    mm144(dA4_, dA3_, dA_, t);

    double h = sh, h2 = h*h, h3 = h2*h, h4 = h3*h;
    if (t < 144) {
        int r = t / 12, c = t % 12;
        dM_[t] = (r == c ? 1.0 : 0.0) + h*dA_[t] + h2/2.0*dA2_[t] + h3/6.0*dA3_[t] + h4/24.0*dA4_[t];
    }
    if (t < 12) {
        int r = t;
        double ab0=0,a2b0=0,a3b0=0,abq=0,a2bq=0,a3bq=0;
        #pragma unroll
        for (int k = 0; k < 12; k++) {
            ab0  += dA_ [r*12+k]*sb0[k];  a2b0 += dA2_[r*12+k]*sb0[k];  a3b0 += dA3_[r*12+k]*sb0[k];
            abq  += dA_ [r*12+k]*sBq[k];  a2bq += dA2_[r*12+k]*sBq[k];  a3bq += dA3_[r*12+k]*sBq[k];
        }
        g_ptv[r] = (float)(h/2.0*sb0[r] + h2/3.0*ab0 + h3/8.0*a2b0 + h4/24.0*a3b0);
        g_qtv[r] = (float)(h/2.0*sb0[r] + h2/6.0*ab0 + h3/24.0*a2b0);
        g_vv [r] = (float)(h*sBq[r] + h2/2.0*abq + h3/6.0*a2bq + h4/24.0*a3bq);
    }
    __syncthreads();

    // ML = M^27 = M16*M8*M2*M
    mm144(dP2_,  dM_,   dM_,   t);
    mm144(dP4_,  dP2_,  dP2_,  t);
    mm144(dP8_,  dP4_,  dP4_,  t);
    mm144(dP16_, dP8_,  dP8_,  t);
    mm144(dT1_,  dP16_, dP8_,  t);   // M^24
    mm144(dT2_,  dT1_,  dP2_,  t);   // M^26
    mm144(dML_,  dT2_,  dM_,   t);   // M^27

    // W0 = ML^37 = ML^32 * ML^4 * ML  (group transfer matrix = M^999)
    mm144(dP2_,  dML_,  dML_,  t);   // ML^2
    mm144(dP4_,  dP2_,  dP2_,  t);   // ML^4
    mm144(dP8_,  dP4_,  dP4_,  t);   // ML^8
    mm144(dP16_, dP8_,  dP8_,  t);   // ML^16
    mm144(dT1_,  dP16_, dP16_, t);   // ML^32
    mm144(dT2_,  dT1_,  dP4_,  t);   // ML^36
    mm144(dW_[0], dT2_, dML_,  t);   // ML^37
    for (int k = 1; k < 10; k++) mm144(dW_[k], dW_[k-1], dW_[k-1], t);

    if (t < 144) {
        int r = t / 12, c = t % 12, ci = c*12 + r;      // store column-major
        g_Mcol [ci] = (float)dM_ [t];
        g_MLcol[ci] = (float)dML_[t];
        #pragma unroll
        for (int k = 0; k < 10; k++) g_Wcol[k*144 + ci] = (float)dW_[k][t];
    }
}

// ---------------- fused RK4 step: x <- M x + pt*tot + qt*ton + v ----------------
__device__ __forceinline__ void stepM(float s[12], const float* __restrict__ sM,
                                      const float* __restrict__ sPt, const float* __restrict__ sQt,
                                      const float* __restrict__ sV, float tot, float ton) {
    float ns[12];
    #pragma unroll
    for (int r = 0; r < 12; r++) ns[r] = fmaf(sPt[r], tot, fmaf(sQt[r], ton, sV[r]));
    #pragma unroll
    for (int j = 0; j < 12; j++) {
        float xj = s[j];
        #pragma unroll
        for (int r = 0; r < 12; r++) ns[r] = fmaf(sM[j*12 + r], xj, ns[r]);
    }
    #pragma unroll
    for (int r = 0; r < 12; r++) s[r] = ns[r];
}

// ---------------- K1: per-chunk forcing prefix F_c ----------------
__global__ void __launch_bounds__(BLK) k_phaseB(const float* __restrict__ Tout,
                                                const float* __restrict__ x0) {
    __shared__ float sM[144], sPt[12], sQt[12], sV[12];
    __shared__ float sTo[BLK*L_CH + 1];
    int tid = threadIdx.x;
    for (int i = tid; i < 144; i += BLK) sM[i] = g_Mcol[i];
    if (tid < 12) { sPt[tid] = g_ptv[tid]; sQt[tid] = g_qtv[tid]; sV[tid] = g_vv[tid]; }
    int base = blockIdx.x * (BLK*L_CH);
    for (int i = tid; i < BLK*L_CH + 1; i += BLK) {
        int gi = base + i; if (gi > T_LEN-1) gi = T_LEN-1;
        sTo[i] = Tout[gi];
    }
    __syncthreads();

    int c = blockIdx.x * BLK + tid;
    float s[12];
    #pragma unroll
    for (int r = 0; r < 12; r++) s[r] = 0.f;
    if (c == 0) {
        #pragma unroll
        for (int r = 0; r < 12; r++) s[r] = x0[r];   // fold x0 into chunk 0
    }
    int off = tid * L_CH;
    float tot = sTo[off];
    #pragma unroll 1
    for (int i = 0; i < L_CH; i++) {
        float ton = sTo[off + i + 1];
        stepM(s, sM, sPt, sQt, sV, tot, ton);
        tot = ton;
    }
    g_F[c*3+0] = make_float4(s[0], s[1], s[2],  s[3]);
    g_F[c*3+1] = make_float4(s[4], s[5], s[6],  s[7]);
    g_F[c*3+2] = make_float4(s[8], s[9], s[10], s[11]);
}

// affine fold helper: t <- ML * t + F
__device__ __forceinline__ void affineFold(float t[12], const float4 f0, const float4 f1,
                                           const float4 f2, const float* __restrict__ sML) {
    float fv[12] = {f0.x,f0.y,f0.z,f0.w, f1.x,f1.y,f1.z,f1.w, f2.x,f2.y,f2.z,f2.w};
    float ns[12];
    #pragma unroll
    for (int r = 0; r < 12; r++) ns[r] = fv[r];
    #pragma unroll
    for (int j = 0; j < 12; j++) {
        float xj = t[j];
        #pragma unroll
        for (int r = 0; r < 12; r++) ns[r] = fmaf(sML[j*12 + r], xj, ns[r]);
    }
    #pragma unroll
    for (int r = 0; r < 12; r++) t[r] = ns[r];
}

// ---------------- K2: group aggregates H_g (fold 37 chunks with M^27) ----------------
__global__ void k_group(void) {
    __shared__ float sML[144];
    int tid = threadIdx.x;
    for (int i = tid; i < 144; i += 32) sML[i] = g_MLcol[i];
    __syncthreads();
    int g = blockIdx.x * 32 + tid;
    float t[12];
    #pragma unroll
    for (int r = 0; r < 12; r++) t[r] = 0.f;
    #pragma unroll 1
    for (int j = 0; j < GRP; j++) {
        int c = g * GRP + j;
        affineFold(t, g_F[c*3], g_F[c*3+1], g_F[c*3+2], sML);
    }
    g_H[g*3+0] = make_float4(t[0], t[1], t[2],  t[3]);
    g_H[g*3+1] = make_float4(t[4], t[5], t[6],  t[7]);
    g_H[g*3+2] = make_float4(t[8], t[9], t[10], t[11]);
}

// ---------------- K3: Kogge-Stone inclusive scan over 1024 groups ----------------
__global__ void __launch_bounds__(1024) k_scan(void) {
    __shared__ float sW[10*144];
    int g = threadIdx.x;
    for (int i = g; i < 10*144; i += 1024) sW[i] = g_Wcol[i];
    float s[12];
    {
        float4 a = g_H[g*3], b = g_H[g*3+1], c = g_H[g*3+2];
        s[0]=a.x; s[1]=a.y; s[2]=a.z; s[3]=a.w;
        s[4]=b.x; s[5]=b.y; s[6]=b.z; s[7]=b.w;
        s[8]=c.x; s[9]=c.y; s[10]=c.z; s[11]=c.w;
    }
    __syncthreads();
    float4* Pin  = g_P0;
    float4* Pout = g_P1;
    Pin[g*3+0] = make_float4(s[0],s[1],s[2],s[3]);
    Pin[g*3+1] = make_float4(s[4],s[5],s[6],s[7]);
    Pin[g*3+2] = make_float4(s[8],s[9],s[10],s[11]);
    __syncthreads();
    #pragma unroll 1
    for (int k = 0; k < 10; k++) {
        int d = 1 << k;
        if (g >= d) {
            float4 a = Pin[(g-d)*3], b = Pin[(g-d)*3+1], c = Pin[(g-d)*3+2];
            float p[12] = {a.x,a.y,a.z,a.w, b.x,b.y,b.z,b.w, c.x,c.y,c.z,c.w};
            #pragma unroll
            for (int j = 0; j < 12; j++) {
                float xj = p[j];
                #pragma unroll
                for (int r = 0; r < 12; r++) s[r] = fmaf(sW[k*144 + j*12 + r], xj, s[r]);
            }
        }
        Pout[g*3+0] = make_float4(s[0],s[1],s[2],s[3]);
        Pout[g*3+1] = make_float4(s[4],s[5],s[6],s[7]);
        Pout[g*3+2] = make_float4(s[8],s[9],s[10],s[11]);
        __syncthreads();
        float4* tmp = Pin; Pin = Pout; Pout = tmp;
    }
    g_Pf[g*3+0] = make_float4(s[0],s[1],s[2],s[3]);
    g_Pf[g*3+1] = make_float4(s[4],s[5],s[6],s[7]);
    g_Pf[g*3+2] = make_float4(s[8],s[9],s[10],s[11]);
}

// ---------------- K4: expand group prefixes to all chunk-end states G_c ----------------
__global__ void k_expand(void) {
    __shared__ float sML[144];
    int tid = threadIdx.x;
    for (int i = tid; i < 144; i += 32) sML[i] = g_MLcol[i];
    __syncthreads();
    int g = blockIdx.x * 32 + tid;
    float t[12];
    if (g == 0) {
        #pragma unroll
        for (int r = 0; r < 12; r++) t[r] = 0.f;
    } else {
        float4 a = g_Pf[(g-1)*3], b = g_Pf[(g-1)*3+1], c = g_Pf[(g-1)*3+2];
        t[0]=a.x; t[1]=a.y; t[2]=a.z; t[3]=a.w;
        t[4]=b.x; t[5]=b.y; t[6]=b.z; t[7]=b.w;
        t[8]=c.x; t[9]=c.y; t[10]=c.z; t[11]=c.w;
    }
    #pragma unroll 1
    for (int j = 0; j < GRP; j++) {
        int c = g * GRP + j;
        affineFold(t, g_F[c*3], g_F[c*3+1], g_F[c*3+2], sML);
        g_G[c*3+0] = make_float4(t[0], t[1], t[2],  t[3]);
        g_G[c*3+1] = make_float4(t[4], t[5], t[6],  t[7]);
        g_G[c*3+2] = make_float4(t[8], t[9], t[10], t[11]);
    }
}

// ---------------- K5: final pass, write all outputs ----------------
__global__ void __launch_bounds__(BLK) k_phaseD(const float* __restrict__ Tout,
                                                const float* __restrict__ x0,
                                                float4* __restrict__ out4) {
    __shared__ float sM[144], sPt[12], sQt[12], sV[12];
    __shared__ float sTo[BLK*L_CH + 1];
    int tid = threadIdx.x;
    for (int i = tid; i < 144; i += BLK) sM[i] = g_Mcol[i];
    if (tid < 12) { sPt[tid] = g_ptv[tid]; sQt[tid] = g_qtv[tid]; sV[tid] = g_vv[tid]; }
    int base = blockIdx.x * (BLK*L_CH);
    for (int i = tid; i < BLK*L_CH + 1; i += BLK) {
        int gi = base + i; if (gi > T_LEN-1) gi = T_LEN-1;
        sTo[i] = Tout[gi];
    }
    __syncthreads();

    int c = blockIdx.x * BLK + tid;
    float s[12];
    if (c == 0) {
        #pragma unroll
        for (int r = 0; r < 12; r++) s[r] = x0[r];
        out4[0] = make_float4(s[0], s[1], s[2],  s[3]);    // row 0 = x0
        out4[1] = make_float4(s[4], s[5], s[6],  s[7]);
        out4[2] = make_float4(s[8], s[9], s[10], s[11]);
    } else {
        float4 a = g_G[(c-1)*3], b = g_G[(c-1)*3+1], cc = g_G[(c-1)*3+2];
        s[0]=a.x; s[1]=a.y; s[2]=a.z; s[3]=a.w;
        s[4]=b.x; s[5]=b.y; s[6]=b.z; s[7]=b.w;
        s[8]=cc.x; s[9]=cc.y; s[10]=cc.z; s[11]=cc.w;
    }

    int n0 = c * L_CH;
    int nmax = S_LEN - n0;
    if (nmax < 0) nmax = 0;
    if (nmax > L_CH) nmax = L_CH;

    int off = tid * L_CH;
    float tot = sTo[off];
    #pragma unroll 1
    for (int i = 0; i < nmax; i++) {
        float ton = sTo[off + i + 1];
        stepM(s, sM, sPt, sQt, sV, tot, ton);
        tot = ton;
        int n1 = n0 + i + 1;
        out4[n1*3+0] = make_float4(s[0], s[1], s[2],  s[3]);
        out4[n1*3+1] = make_float4(s[4], s[5], s[6],  s[7]);
        out4[n1*3+2] = make_float4(s[8], s[9], s[10], s[11]);
    }
}

// ---------------- launch ----------------
extern "C" void kernel_launch(void* const* d_in, const int* in_sizes, int n_in,
                              void* d_out, int out_size) {
    const float* t_eval = (const float*)d_in[0];
    const float* x0     = (const float*)d_in[1];
    const float* A      = (const float*)d_in[2];
    const float* B      = (const float*)d_in[3];
    const float* Tout   = (const float*)d_in[4];
    const float* loads  = (const float*)d_in[5];
    const float* areas  = (const float*)d_in[6];
    float4* out4 = (float4*)d_out;

    k_setup <<<1,    256>>>(t_eval, A, B, loads, areas);
    k_phaseB<<<NBLK, BLK>>>(Tout, x0);
    k_group <<<32,   32 >>>();
    k_scan  <<<1,    1024>>>();
    k_expand<<<32,   32 >>>();
    k_phaseD<<<NBLK, BLK>>>(Tout, x0, out4);
}